// round 4
// baseline (speedup 1.0000x reference)
#include <cuda_runtime.h>

#define N_NODES 8192
#define C_CH    128
#define N_EDGES 262144

// ---------------- scratch (device globals; no allocation allowed) ----------------
__device__ __align__(16) float g_dis[N_NODES];
__device__ __align__(16) int   g_cnt[N_NODES];
__device__ __align__(16) int   g_off[N_NODES];
__device__ __align__(16) int   g_cur[N_NODES];
__device__ __align__(16) int2  g_csr[N_EDGES];        // {src, bitcast(weight)}
__device__ __align__(16) float g_h  [N_NODES * C_CH]; // pre-aggregation x@W
__device__ __align__(16) float g_s  [N_NODES * C_CH];
__device__ __align__(16) float g_t  [N_NODES * C_CH];
__device__ __align__(16) float g_u1 [N_NODES * C_CH];
__device__ __align__(16) float g_u2 [N_NODES * C_CH];
__device__ __align__(16) float g_tt [C_CH * N_NODES]; // T transposed (k-major)
__device__ int g_is64;                                // edge_index dtype flag

// device-side scratch-buffer selection (no cudaGetSymbolAddress on host)
__device__ __forceinline__ float* buf_ptr(int s) {
    switch (s) {
        case 1: return g_s;
        case 2: return g_t;
        case 3: return g_u1;
        case 4: return g_u2;
        default: return g_h;
    }
}

// ---------------- edge_index dtype detection ----------------
// If the buffer holds int64 node-ids (<8192, little-endian), every odd 32-bit
// word inside the first 2*E words is a zero high-half. If it holds int32 ids,
// odd words are src ids (random in [0,8192)) and their OR is nonzero w.p. ~1.
// Only reads within the first 2*E 32-bit words -> in bounds for BOTH dtypes.
__global__ void k_detect(const int* __restrict__ v) {
    __shared__ int any;
    if (threadIdx.x == 0) any = 0;
    __syncthreads();
    int acc = 0;
    for (int i = threadIdx.x; i < 8192; i += 256) {
        int idx = i * 64 + 1;            // odd index, max 524225 < 2*E = 524288
        acc |= v[idx];
    }
    if (acc) atomicOr(&any, 1);
    __syncthreads();
    if (threadIdx.x == 0) g_is64 = (any == 0) ? 1 : 0;
}

__device__ __forceinline__ int edge_at(const void* ei, int idx) {
    int v;
    if (g_is64) v = (int)((const long long*)ei)[idx];
    else        v = ((const int*)ei)[idx];
    return v & (N_NODES - 1);            // safety mask: never out of node range
}

// ---------------- graph preprocessing ----------------
__global__ void k_zero_cnt() {
    int i = blockIdx.x * blockDim.x + threadIdx.x;
    if (i < N_NODES) g_cnt[i] = 0;
}

__global__ void k_deg(const void* __restrict__ ei) {
    int e = blockIdx.x * blockDim.x + threadIdx.x;
    if (e < N_EDGES) {
        int d = edge_at(ei, N_EDGES + e);
        atomicAdd(&g_cnt[d], 1);
    }
}

__global__ void k_dis() {
    int i = blockIdx.x * blockDim.x + threadIdx.x;
    if (i < N_NODES) g_dis[i] = rsqrtf((float)g_cnt[i] + 1.0f);
}

// single-block exclusive scan over 8192 counts -> offsets (+ cursor copy)
__global__ void k_scan() {
    __shared__ int part[1024];
    int t = threadIdx.x;
    int base = t * 8;
    int loc[8];
    int s = 0;
#pragma unroll
    for (int i = 0; i < 8; i++) { loc[i] = g_cnt[base + i]; s += loc[i]; }
    part[t] = s;
    __syncthreads();
    for (int off = 1; off < 1024; off <<= 1) {
        int v = 0;
        if (t >= off) v = part[t - off];
        __syncthreads();
        part[t] += v;
        __syncthreads();
    }
    int run = part[t] - s;   // exclusive prefix for this thread's chunk
#pragma unroll
    for (int i = 0; i < 8; i++) {
        g_off[base + i] = run;
        g_cur[base + i] = run;
        run += loc[i];
    }
}

__global__ void k_fill(const void* __restrict__ ei) {
    int e = blockIdx.x * blockDim.x + threadIdx.x;
    if (e < N_EDGES) {
        int s = edge_at(ei, e);
        int d = edge_at(ei, N_EDGES + e);
        float w = g_dis[s] * g_dis[d];
        int p = atomicAdd(&g_cur[d], 1);
        if (p < N_EDGES) g_csr[p] = make_int2(s, __float_as_int(w));
    }
}

// ---------------- dense GEMM: g_h[8192,128] = A[8192,128] @ W[128,128] ----------------
// BM=64, 256 threads, 4x8 micro-tile, K chunked by 32, static smem (26KB)
__global__ __launch_bounds__(256) void k_gemm_small(const float* __restrict__ Aext,
                                                    int selA,
                                                    const float* __restrict__ W) {
    __shared__ float Wsm[32 * 128];   // [k][n]
    __shared__ float Asm[64 * 40];    // [m][k] padded

    const float* A = Aext ? Aext : buf_ptr(selA);
    int tid = threadIdx.x;
    int rb  = blockIdx.x * 64;
    int cg = tid & 15, rg = tid >> 4;
    int r0 = rg * 4, c0 = cg * 8;

    float acc[4][8];
#pragma unroll
    for (int i = 0; i < 4; i++)
#pragma unroll
        for (int j = 0; j < 8; j++) acc[i][j] = 0.f;

    for (int c = 0; c < 4; c++) {
        int kc0 = c * 32;
        __syncthreads();
#pragma unroll
        for (int i = 0; i < 4; i++) {          // W tile: 32x128 = 1024 f4
            int idx = tid + i * 256;
            int k = idx >> 5, c4 = idx & 31;
            *(float4*)&Wsm[k * 128 + c4 * 4] =
                *(const float4*)&W[(size_t)(kc0 + k) * 128 + c4 * 4];
        }
#pragma unroll
        for (int i = 0; i < 2; i++) {          // A tile: 64x32 = 512 f4
            int idx = tid + i * 256;
            int row = idx >> 3, c4 = idx & 7;
            *(float4*)&Asm[row * 40 + c4 * 4] =
                *(const float4*)&A[(size_t)(rb + row) * 128 + kc0 + c4 * 4];
        }
        __syncthreads();

#pragma unroll
        for (int k = 0; k < 32; k += 4) {
            float4 a[4];
#pragma unroll
            for (int i = 0; i < 4; i++) a[i] = *(const float4*)&Asm[(r0 + i) * 40 + k];
#pragma unroll
            for (int kk = 0; kk < 4; kk++) {
                float4 bLo = *(const float4*)&Wsm[(k + kk) * 128 + c0];
                float4 bHi = *(const float4*)&Wsm[(k + kk) * 128 + c0 + 4];
                float bv[8] = {bLo.x, bLo.y, bLo.z, bLo.w, bHi.x, bHi.y, bHi.z, bHi.w};
#pragma unroll
                for (int i = 0; i < 4; i++) {
                    float av = (kk == 0) ? a[i].x : (kk == 1) ? a[i].y
                               : (kk == 2) ? a[i].z : a[i].w;
#pragma unroll
                    for (int j = 0; j < 8; j++)
                        acc[i][j] = fmaf(av, bv[j], acc[i][j]);
                }
            }
        }
    }

#pragma unroll
    for (int i = 0; i < 4; i++) {
        float4 lo = make_float4(acc[i][0], acc[i][1], acc[i][2], acc[i][3]);
        float4 hi = make_float4(acc[i][4], acc[i][5], acc[i][6], acc[i][7]);
        size_t base = (size_t)(rb + r0 + i) * 128 + c0;
        *(float4*)&g_h[base]     = lo;
        *(float4*)&g_h[base + 4] = hi;
    }
}

// ---------------- GCN aggregation: O[n] = sum_e w_e*h[src] + dis^2*h[n] + b ----------------
// one warp per node, lanes cover 128 channels as float4
__global__ __launch_bounds__(256) void k_agg(const float* __restrict__ bias,
                                             float* __restrict__ Oext, int selO,
                                             int relu) {
    float* O = Oext ? Oext : buf_ptr(selO);
    int warp = threadIdx.x >> 5, lane = threadIdx.x & 31;
    int node = blockIdx.x * 8 + warp;
    const float4* H4 = (const float4*)g_h;

    float4 bb = ((const float4*)bias)[lane];
    float  di = g_dis[node];
    float  dd = di * di;
    float4 h  = H4[(size_t)node * 32 + lane];
    float4 acc;
    acc.x = fmaf(h.x, dd, bb.x);
    acc.y = fmaf(h.y, dd, bb.y);
    acc.z = fmaf(h.z, dd, bb.z);
    acc.w = fmaf(h.w, dd, bb.w);
    float4 acc2 = make_float4(0.f, 0.f, 0.f, 0.f);

    int start = g_off[node];
    int cnt   = g_cnt[node];
    int j = 0;
    for (; j + 1 < cnt; j += 2) {
        int2 e0 = g_csr[start + j];
        int2 e1 = g_csr[start + j + 1];
        float w0 = __int_as_float(e0.y);
        float w1 = __int_as_float(e1.y);
        float4 v0 = H4[(size_t)e0.x * 32 + lane];
        float4 v1 = H4[(size_t)e1.x * 32 + lane];
        acc.x  = fmaf(v0.x, w0, acc.x);  acc.y  = fmaf(v0.y, w0, acc.y);
        acc.z  = fmaf(v0.z, w0, acc.z);  acc.w  = fmaf(v0.w, w0, acc.w);
        acc2.x = fmaf(v1.x, w1, acc2.x); acc2.y = fmaf(v1.y, w1, acc2.y);
        acc2.z = fmaf(v1.z, w1, acc2.z); acc2.w = fmaf(v1.w, w1, acc2.w);
    }
    if (j < cnt) {
        int2 e0 = g_csr[start + j];
        float w0 = __int_as_float(e0.y);
        float4 v0 = H4[(size_t)e0.x * 32 + lane];
        acc.x = fmaf(v0.x, w0, acc.x); acc.y = fmaf(v0.y, w0, acc.y);
        acc.z = fmaf(v0.z, w0, acc.z); acc.w = fmaf(v0.w, w0, acc.w);
    }
    acc.x += acc2.x; acc.y += acc2.y; acc.z += acc2.z; acc.w += acc2.w;

    if (relu) {
        acc.x = fmaxf(acc.x, 0.f); acc.y = fmaxf(acc.y, 0.f);
        acc.z = fmaxf(acc.z, 0.f); acc.w = fmaxf(acc.w, 0.f);
    }
    ((float4*)O)[(size_t)node * 32 + lane] = acc;
}

// ---------------- transpose g_t[8192,128] -> g_tt[128,8192] ----------------
__global__ void k_transpose() {
    __shared__ float tile[32][33];
    int n0 = blockIdx.x * 32, k0 = blockIdx.y * 32;
    int tx = threadIdx.x, ty = threadIdx.y;
#pragma unroll
    for (int j = 0; j < 32; j += 8)
        tile[ty + j][tx] = g_t[(size_t)(n0 + ty + j) * 128 + (k0 + tx)];
    __syncthreads();
#pragma unroll
    for (int j = 0; j < 32; j += 8)
        g_tt[(size_t)(k0 + ty + j) * 8192 + (n0 + tx)] = tile[tx][ty + j];
}

// ---------------- decoder GEMM: adj[8192,8192] = g_s @ g_t^T (via g_tt) ----------------
// BM=BN=128, 256 threads, 8x8 micro, K chunked by 32, static smem (36.5KB)
__global__ __launch_bounds__(256) void k_gemm_big(float* __restrict__ adj) {
    __shared__ float Bsm[32 * 128];   // [k][n]
    __shared__ float Asm[128 * 40];   // [m][k] padded

    int tid = threadIdx.x;
    int cb = blockIdx.x * 128;
    int rb = blockIdx.y * 128;
    int cg = tid & 15, rg = tid >> 4;
    int r0 = rg * 8, c0 = cg * 8;

    float acc[8][8];
#pragma unroll
    for (int i = 0; i < 8; i++)
#pragma unroll
        for (int j = 0; j < 8; j++) acc[i][j] = 0.f;

    for (int c = 0; c < 4; c++) {
        int kc0 = c * 32;
        __syncthreads();
#pragma unroll
        for (int i = 0; i < 4; i++) {          // A tile: 128x32 = 1024 f4
            int idx = tid + i * 256;
            int row = idx >> 3, c4 = idx & 7;
            *(float4*)&Asm[row * 40 + c4 * 4] =
                *(const float4*)&g_s[(size_t)(rb + row) * 128 + kc0 + c4 * 4];
        }
#pragma unroll
        for (int i = 0; i < 4; i++) {          // B tile: 32x128 = 1024 f4
            int idx = tid + i * 256;
            int k = idx >> 5, c4 = idx & 31;
            *(float4*)&Bsm[k * 128 + c4 * 4] =
                *(const float4*)&g_tt[(size_t)(kc0 + k) * 8192 + cb + c4 * 4];
        }
        __syncthreads();

#pragma unroll
        for (int k = 0; k < 32; k += 2) {
#pragma unroll
            for (int kk = 0; kk < 2; kk++) {
                float4 bLo = *(const float4*)&Bsm[(k + kk) * 128 + c0];
                float4 bHi = *(const float4*)&Bsm[(k + kk) * 128 + c0 + 4];
                float bv[8] = {bLo.x, bLo.y, bLo.z, bLo.w, bHi.x, bHi.y, bHi.z, bHi.w};
#pragma unroll
                for (int i = 0; i < 8; i++) {
                    float av = Asm[(r0 + i) * 40 + k + kk];
#pragma unroll
                    for (int j = 0; j < 8; j++)
                        acc[i][j] = fmaf(av, bv[j], acc[i][j]);
                }
            }
        }
    }

#pragma unroll
    for (int i = 0; i < 8; i++) {
        float4 lo = make_float4(acc[i][0], acc[i][1], acc[i][2], acc[i][3]);
        float4 hi = make_float4(acc[i][4], acc[i][5], acc[i][6], acc[i][7]);
        size_t base = (size_t)(rb + r0 + i) * 8192 + cb + c0;
        *(float4*)&adj[base]     = lo;
        *(float4*)&adj[base + 4] = hi;
    }
}

// ---------------- launch: kernel launches ONLY, no other CUDA API ----------------
extern "C" void kernel_launch(void* const* d_in, const int* in_sizes, int n_in,
                              void* d_out, int out_size) {
    (void)in_sizes; (void)n_in;
    const float* x  = (const float*)d_in[0];
    const void*  ei = d_in[1];
    const float *Ws = (const float*)d_in[2],  *bs  = (const float*)d_in[3];
    const float *Wt = (const float*)d_in[4],  *bt  = (const float*)d_in[5];
    const float *W1 = (const float*)d_in[6],  *b1  = (const float*)d_in[7];
    const float *W2 = (const float*)d_in[8],  *b2  = (const float*)d_in[9];
    const float *Wmu= (const float*)d_in[10], *bmu = (const float*)d_in[11];
    const float *W5 = (const float*)d_in[12], *b5  = (const float*)d_in[13];
    const float *W6 = (const float*)d_in[14], *b6  = (const float*)d_in[15];

    float* adj  = (float*)d_out;
    float* hout = (float*)d_out + ((size_t)out_size - (size_t)N_NODES * C_CH);

    // graph preprocessing
    k_detect<<<1, 256>>>((const int*)ei);
    k_zero_cnt<<<N_NODES / 256, 256>>>();
    k_deg<<<N_EDGES / 256, 256>>>(ei);
    k_dis<<<N_NODES / 256, 256>>>();
    k_scan<<<1, 1024>>>();
    k_fill<<<N_EDGES / 256, 256>>>(ei);

    // GCN layers: gemm (writes g_h) then aggregate (+bias, +self-loop, opt relu)
    // sel: 1=g_s 2=g_t 3=g_u1 4=g_u2
    k_gemm_small<<<128, 256>>>(x,       0, Ws);  k_agg<<<1024, 256>>>(bs,  nullptr, 1, 0);
    k_gemm_small<<<128, 256>>>(x,       0, Wt);  k_agg<<<1024, 256>>>(bt,  nullptr, 2, 0);
    k_gemm_small<<<128, 256>>>(x,       0, W1);  k_agg<<<1024, 256>>>(b1,  nullptr, 3, 1);
    k_gemm_small<<<128, 256>>>(nullptr, 3, W2);  k_agg<<<1024, 256>>>(b2,  nullptr, 4, 1);
    k_gemm_small<<<128, 256>>>(nullptr, 4, Wmu); k_agg<<<1024, 256>>>(bmu, nullptr, 3, 0);
    k_gemm_small<<<128, 256>>>(nullptr, 3, W5);  k_agg<<<1024, 256>>>(b5,  nullptr, 4, 1);
    k_gemm_small<<<128, 256>>>(nullptr, 4, W6);  k_agg<<<1024, 256>>>(b6,  hout,    0, 1);

    // decoder: adj = s @ t^T
    k_transpose<<<dim3(256, 4), dim3(32, 8)>>>();
    k_gemm_big<<<dim3(64, 64), 256>>>(adj);
}

// round 5
// speedup vs baseline: 1.5137x; 1.5137x over previous
#include <cuda_runtime.h>
#include <cuda_bf16.h>
#include <cstdint>

#define N_NODES 8192
#define C_CH    128
#define N_EDGES 262144

// ---------------- scratch (device globals; no allocation allowed) ----------------
__device__ __align__(16) float g_dis[N_NODES];
__device__ __align__(16) int   g_cnt[N_NODES];
__device__ __align__(16) int   g_off[N_NODES];
__device__ __align__(16) int   g_cur[N_NODES];
__device__ __align__(16) int2  g_csr[N_EDGES];        // {src, bitcast(weight)}
__device__ __align__(16) float g_h  [N_NODES * C_CH]; // pre-aggregation x@W
__device__ __align__(16) float g_s  [N_NODES * C_CH];
__device__ __align__(16) float g_t  [N_NODES * C_CH];
__device__ __align__(16) float g_u1 [N_NODES * C_CH];
__device__ __align__(16) float g_u2 [N_NODES * C_CH];
// split-bf16 operands for the tensor-core decoder
__device__ __align__(16) __nv_bfloat16 g_sh[N_NODES * C_CH];
__device__ __align__(16) __nv_bfloat16 g_sl[N_NODES * C_CH];
__device__ __align__(16) __nv_bfloat16 g_th[N_NODES * C_CH];
__device__ __align__(16) __nv_bfloat16 g_tl[N_NODES * C_CH];
__device__ int g_is64;                                // edge_index dtype flag

// device-side scratch-buffer selection (no cudaGetSymbolAddress on host)
__device__ __forceinline__ float* buf_ptr(int s) {
    switch (s) {
        case 1: return g_s;
        case 2: return g_t;
        case 3: return g_u1;
        case 4: return g_u2;
        default: return g_h;
    }
}

// ---------------- edge_index dtype detection ----------------
__global__ void k_detect(const int* __restrict__ v) {
    __shared__ int any;
    if (threadIdx.x == 0) any = 0;
    __syncthreads();
    int acc = 0;
    for (int i = threadIdx.x; i < 8192; i += 256) {
        int idx = i * 64 + 1;            // odd index, max 524225 < 2*E
        acc |= v[idx];
    }
    if (acc) atomicOr(&any, 1);
    __syncthreads();
    if (threadIdx.x == 0) g_is64 = (any == 0) ? 1 : 0;
}

__device__ __forceinline__ int edge_at(const void* ei, int idx) {
    int v;
    if (g_is64) v = (int)((const long long*)ei)[idx];
    else        v = ((const int*)ei)[idx];
    return v & (N_NODES - 1);
}

// ---------------- graph preprocessing ----------------
__global__ void k_zero_cnt() {
    int i = blockIdx.x * blockDim.x + threadIdx.x;
    if (i < N_NODES) g_cnt[i] = 0;
}

__global__ void k_deg(const void* __restrict__ ei) {
    int e = blockIdx.x * blockDim.x + threadIdx.x;
    if (e < N_EDGES) {
        int d = edge_at(ei, N_EDGES + e);
        atomicAdd(&g_cnt[d], 1);
    }
}

__global__ void k_dis() {
    int i = blockIdx.x * blockDim.x + threadIdx.x;
    if (i < N_NODES) g_dis[i] = rsqrtf((float)g_cnt[i] + 1.0f);
}

__global__ void k_scan() {
    __shared__ int part[1024];
    int t = threadIdx.x;
    int base = t * 8;
    int loc[8];
    int s = 0;
#pragma unroll
    for (int i = 0; i < 8; i++) { loc[i] = g_cnt[base + i]; s += loc[i]; }
    part[t] = s;
    __syncthreads();
    for (int off = 1; off < 1024; off <<= 1) {
        int v = 0;
        if (t >= off) v = part[t - off];
        __syncthreads();
        part[t] += v;
        __syncthreads();
    }
    int run = part[t] - s;
#pragma unroll
    for (int i = 0; i < 8; i++) {
        g_off[base + i] = run;
        g_cur[base + i] = run;
        run += loc[i];
    }
}

__global__ void k_fill(const void* __restrict__ ei) {
    int e = blockIdx.x * blockDim.x + threadIdx.x;
    if (e < N_EDGES) {
        int s = edge_at(ei, e);
        int d = edge_at(ei, N_EDGES + e);
        float w = g_dis[s] * g_dis[d];
        int p = atomicAdd(&g_cur[d], 1);
        if (p < N_EDGES) g_csr[p] = make_int2(s, __float_as_int(w));
    }
}

// ---------------- dense GEMM: g_h[8192,128] = A[8192,128] @ W[128,128] ----------------
__global__ __launch_bounds__(256) void k_gemm_small(const float* __restrict__ Aext,
                                                    int selA,
                                                    const float* __restrict__ W) {
    __shared__ float Wsm[32 * 128];
    __shared__ float Asm[64 * 40];

    const float* A = Aext ? Aext : buf_ptr(selA);
    int tid = threadIdx.x;
    int rb  = blockIdx.x * 64;
    int cg = tid & 15, rg = tid >> 4;
    int r0 = rg * 4, c0 = cg * 8;

    float acc[4][8];
#pragma unroll
    for (int i = 0; i < 4; i++)
#pragma unroll
        for (int j = 0; j < 8; j++) acc[i][j] = 0.f;

    for (int c = 0; c < 4; c++) {
        int kc0 = c * 32;
        __syncthreads();
#pragma unroll
        for (int i = 0; i < 4; i++) {
            int idx = tid + i * 256;
            int k = idx >> 5, c4 = idx & 31;
            *(float4*)&Wsm[k * 128 + c4 * 4] =
                *(const float4*)&W[(size_t)(kc0 + k) * 128 + c4 * 4];
        }
#pragma unroll
        for (int i = 0; i < 2; i++) {
            int idx = tid + i * 256;
            int row = idx >> 3, c4 = idx & 7;
            *(float4*)&Asm[row * 40 + c4 * 4] =
                *(const float4*)&A[(size_t)(rb + row) * 128 + kc0 + c4 * 4];
        }
        __syncthreads();

#pragma unroll
        for (int k = 0; k < 32; k += 4) {
            float4 a[4];
#pragma unroll
            for (int i = 0; i < 4; i++) a[i] = *(const float4*)&Asm[(r0 + i) * 40 + k];
#pragma unroll
            for (int kk = 0; kk < 4; kk++) {
                float4 bLo = *(const float4*)&Wsm[(k + kk) * 128 + c0];
                float4 bHi = *(const float4*)&Wsm[(k + kk) * 128 + c0 + 4];
                float bv[8] = {bLo.x, bLo.y, bLo.z, bLo.w, bHi.x, bHi.y, bHi.z, bHi.w};
#pragma unroll
                for (int i = 0; i < 4; i++) {
                    float av = (kk == 0) ? a[i].x : (kk == 1) ? a[i].y
                               : (kk == 2) ? a[i].z : a[i].w;
#pragma unroll
                    for (int j = 0; j < 8; j++)
                        acc[i][j] = fmaf(av, bv[j], acc[i][j]);
                }
            }
        }
    }

#pragma unroll
    for (int i = 0; i < 4; i++) {
        float4 lo = make_float4(acc[i][0], acc[i][1], acc[i][2], acc[i][3]);
        float4 hi = make_float4(acc[i][4], acc[i][5], acc[i][6], acc[i][7]);
        size_t base = (size_t)(rb + r0 + i) * 128 + c0;
        *(float4*)&g_h[base]     = lo;
        *(float4*)&g_h[base + 4] = hi;
    }
}

// ---------------- GCN aggregation ----------------
__global__ __launch_bounds__(256) void k_agg(const float* __restrict__ bias,
                                             float* __restrict__ Oext, int selO,
                                             int relu) {
    float* O = Oext ? Oext : buf_ptr(selO);
    int warp = threadIdx.x >> 5, lane = threadIdx.x & 31;
    int node = blockIdx.x * 8 + warp;
    const float4* H4 = (const float4*)g_h;

    float4 bb = ((const float4*)bias)[lane];
    float  di = g_dis[node];
    float  dd = di * di;
    float4 h  = H4[(size_t)node * 32 + lane];
    float4 acc;
    acc.x = fmaf(h.x, dd, bb.x);
    acc.y = fmaf(h.y, dd, bb.y);
    acc.z = fmaf(h.z, dd, bb.z);
    acc.w = fmaf(h.w, dd, bb.w);
    float4 acc2 = make_float4(0.f, 0.f, 0.f, 0.f);

    int start = g_off[node];
    int cnt   = g_cnt[node];
    int j = 0;
    for (; j + 1 < cnt; j += 2) {
        int2 e0 = g_csr[start + j];
        int2 e1 = g_csr[start + j + 1];
        float w0 = __int_as_float(e0.y);
        float w1 = __int_as_float(e1.y);
        float4 v0 = H4[(size_t)e0.x * 32 + lane];
        float4 v1 = H4[(size_t)e1.x * 32 + lane];
        acc.x  = fmaf(v0.x, w0, acc.x);  acc.y  = fmaf(v0.y, w0, acc.y);
        acc.z  = fmaf(v0.z, w0, acc.z);  acc.w  = fmaf(v0.w, w0, acc.w);
        acc2.x = fmaf(v1.x, w1, acc2.x); acc2.y = fmaf(v1.y, w1, acc2.y);
        acc2.z = fmaf(v1.z, w1, acc2.z); acc2.w = fmaf(v1.w, w1, acc2.w);
    }
    if (j < cnt) {
        int2 e0 = g_csr[start + j];
        float w0 = __int_as_float(e0.y);
        float4 v0 = H4[(size_t)e0.x * 32 + lane];
        acc.x = fmaf(v0.x, w0, acc.x); acc.y = fmaf(v0.y, w0, acc.y);
        acc.z = fmaf(v0.z, w0, acc.z); acc.w = fmaf(v0.w, w0, acc.w);
    }
    acc.x += acc2.x; acc.y += acc2.y; acc.z += acc2.z; acc.w += acc2.w;

    if (relu) {
        acc.x = fmaxf(acc.x, 0.f); acc.y = fmaxf(acc.y, 0.f);
        acc.z = fmaxf(acc.z, 0.f); acc.w = fmaxf(acc.w, 0.f);
    }
    ((float4*)O)[(size_t)node * 32 + lane] = acc;
}

// ---------------- split fp32 -> (hi, lo) bf16 for s and t ----------------
__global__ __launch_bounds__(256) void k_split() {
    int i = blockIdx.x * blockDim.x + threadIdx.x;   // 0 .. 2^20-1
    float vs = g_s[i];
    __nv_bfloat16 sh = __float2bfloat16(vs);
    g_sh[i] = sh;
    g_sl[i] = __float2bfloat16(vs - __bfloat162float(sh));
    float vt = g_t[i];
    __nv_bfloat16 th = __float2bfloat16(vt);
    g_th[i] = th;
    g_tl[i] = __float2bfloat16(vt - __bfloat162float(th));
}

// ---------------- tensor-core decoder: adj = S @ T^T, split-bf16, 3 products ----------------
__device__ __forceinline__ void ldsm_x4(uint32_t& r0, uint32_t& r1,
                                        uint32_t& r2, uint32_t& r3, uint32_t a) {
    asm volatile("ldmatrix.sync.aligned.m8n8.x4.shared.b16 {%0,%1,%2,%3}, [%4];"
                 : "=r"(r0), "=r"(r1), "=r"(r2), "=r"(r3) : "r"(a));
}
__device__ __forceinline__ void ldsm_x2(uint32_t& r0, uint32_t& r1, uint32_t a) {
    asm volatile("ldmatrix.sync.aligned.m8n8.x2.shared.b16 {%0,%1}, [%2];"
                 : "=r"(r0), "=r"(r1) : "r"(a));
}
__device__ __forceinline__ void mma_bf16(float& c0, float& c1, float& c2, float& c3,
                                         uint32_t a0, uint32_t a1, uint32_t a2, uint32_t a3,
                                         uint32_t b0, uint32_t b1) {
    asm volatile(
        "mma.sync.aligned.m16n8k16.row.col.f32.bf16.bf16.f32 "
        "{%0,%1,%2,%3}, {%4,%5,%6,%7}, {%8,%9}, {%0,%1,%2,%3};"
        : "+f"(c0), "+f"(c1), "+f"(c2), "+f"(c3)
        : "r"(a0), "r"(a1), "r"(a2), "r"(a3), "r"(b0), "r"(b1));
}

#define SWZ(off) ((off) ^ (((off) >> 3) & 0x70))

__global__ __launch_bounds__(256) void k_decoder(float* __restrict__ adj) {
    // per 32-k chunk: each row = 32 hi bf16 (64B) | 32 lo bf16 (64B) = 128B, SW128 swizzled
    __shared__ __align__(16) __nv_bfloat16 Ssm[128 * 64];
    __shared__ __align__(16) __nv_bfloat16 Tsm[128 * 64];

    int tid = threadIdx.x;
    int lane = tid & 31, wid = tid >> 5;
    int wm = wid >> 2, wn = wid & 3;                 // 2 x 4 warp grid
    int cb = blockIdx.x * 128, rb = blockIdx.y * 128;

    uint32_t sbase = (uint32_t)__cvta_generic_to_shared(Ssm);
    uint32_t tbase = (uint32_t)__cvta_generic_to_shared(Tsm);

    float acc[4][4][4];
#pragma unroll
    for (int m = 0; m < 4; m++)
#pragma unroll
        for (int n = 0; n < 4; n++)
#pragma unroll
            for (int r = 0; r < 4; r++) acc[m][n][r] = 0.f;

    for (int c = 0; c < 4; c++) {
        int kc0 = c * 32;
        __syncthreads();
        // load chunk tiles: 1024 16B-segments per tile, 256 threads x 4
#pragma unroll
        for (int i = 0; i < 4; i++) {
            int seg = tid + i * 256;
            int r = seg >> 3, sgi = seg & 7;
            uint32_t off = (uint32_t)(r * 128 + sgi * 16);
            uint32_t ph = SWZ(off);
            const uint4* srcS;
            const uint4* srcT;
            if (sgi < 4) {
                srcS = (const uint4*)&g_sh[(size_t)(rb + r) * 128 + kc0 + sgi * 8];
                srcT = (const uint4*)&g_th[(size_t)(cb + r) * 128 + kc0 + sgi * 8];
            } else {
                srcS = (const uint4*)&g_sl[(size_t)(rb + r) * 128 + kc0 + (sgi - 4) * 8];
                srcT = (const uint4*)&g_tl[(size_t)(cb + r) * 128 + kc0 + (sgi - 4) * 8];
            }
            *(uint4*)((char*)Ssm + ph) = *srcS;
            *(uint4*)((char*)Tsm + ph) = *srcT;
        }
        __syncthreads();

#pragma unroll
        for (int ks = 0; ks < 2; ks++) {
            // B fragments (hi and lo) for 4 n-tiles
            uint32_t bh[4][2], bl[4][2];
#pragma unroll
            for (int n = 0; n < 4; n++) {
                int row = wn * 32 + n * 8 + (lane & 7);
                int half = (lane >> 3) & 1;
                uint32_t off = (uint32_t)(row * 128 + ks * 32 + half * 16);
                ldsm_x2(bh[n][0], bh[n][1], tbase + SWZ(off));
                uint32_t offl = off + 64;
                ldsm_x2(bl[n][0], bl[n][1], tbase + SWZ(offl));
            }
#pragma unroll
            for (int m = 0; m < 4; m++) {
                int row = wm * 64 + m * 16 + (lane & 15);
                int half = (lane >> 4) & 1;
                uint32_t off = (uint32_t)(row * 128 + ks * 32 + half * 16);
                uint32_t a0, a1, a2, a3;
                ldsm_x4(a0, a1, a2, a3, sbase + SWZ(off));
#pragma unroll
                for (int n = 0; n < 4; n++)
                    mma_bf16(acc[m][n][0], acc[m][n][1], acc[m][n][2], acc[m][n][3],
                             a0, a1, a2, a3, bh[n][0], bh[n][1]);
#pragma unroll
                for (int n = 0; n < 4; n++)
                    mma_bf16(acc[m][n][0], acc[m][n][1], acc[m][n][2], acc[m][n][3],
                             a0, a1, a2, a3, bl[n][0], bl[n][1]);
                uint32_t l0, l1, l2, l3;
                uint32_t offl = off + 64;
                ldsm_x4(l0, l1, l2, l3, sbase + SWZ(offl));
#pragma unroll
                for (int n = 0; n < 4; n++)
                    mma_bf16(acc[m][n][0], acc[m][n][1], acc[m][n][2], acc[m][n][3],
                             l0, l1, l2, l3, bh[n][0], bh[n][1]);
            }
        }
    }

    // epilogue: c frag lane mapping -> rows (lane/4, +8), cols (lane%4)*2, +1
#pragma unroll
    for (int m = 0; m < 4; m++) {
#pragma unroll
        for (int n = 0; n < 4; n++) {
            int row = rb + wm * 64 + m * 16 + (lane >> 2);
            int col = cb + wn * 32 + n * 8 + (lane & 3) * 2;
            float2 v0 = make_float2(acc[m][n][0], acc[m][n][1]);
            float2 v1 = make_float2(acc[m][n][2], acc[m][n][3]);
            *(float2*)&adj[(size_t)row * 8192 + col]       = v0;
            *(float2*)&adj[(size_t)(row + 8) * 8192 + col] = v1;
        }
    }
}

// ---------------- launch: kernel launches ONLY ----------------
extern "C" void kernel_launch(void* const* d_in, const int* in_sizes, int n_in,
                              void* d_out, int out_size) {
    (void)in_sizes; (void)n_in;
    const float* x  = (const float*)d_in[0];
    const void*  ei = d_in[1];
    const float *Ws = (const float*)d_in[2],  *bs  = (const float*)d_in[3];
    const float *Wt = (const float*)d_in[4],  *bt  = (const float*)d_in[5];
    const float *W1 = (const float*)d_in[6],  *b1  = (const float*)d_in[7];
    const float *W2 = (const float*)d_in[8],  *b2  = (const float*)d_in[9];
    const float *Wmu= (const float*)d_in[10], *bmu = (const float*)d_in[11];
    const float *W5 = (const float*)d_in[12], *b5  = (const float*)d_in[13];
    const float *W6 = (const float*)d_in[14], *b6  = (const float*)d_in[15];

    float* adj  = (float*)d_out;
    float* hout = (float*)d_out + ((size_t)out_size - (size_t)N_NODES * C_CH);

    // graph preprocessing
    k_detect<<<1, 256>>>((const int*)ei);
    k_zero_cnt<<<N_NODES / 256, 256>>>();
    k_deg<<<N_EDGES / 256, 256>>>(ei);
    k_dis<<<N_NODES / 256, 256>>>();
    k_scan<<<1, 1024>>>();
    k_fill<<<N_EDGES / 256, 256>>>(ei);

    // GCN layers
    k_gemm_small<<<128, 256>>>(x,       0, Ws);  k_agg<<<1024, 256>>>(bs,  nullptr, 1, 0);
    k_gemm_small<<<128, 256>>>(x,       0, Wt);  k_agg<<<1024, 256>>>(bt,  nullptr, 2, 0);
    k_split<<<(N_NODES * C_CH) / 256, 256>>>();
    k_gemm_small<<<128, 256>>>(x,       0, W1);  k_agg<<<1024, 256>>>(b1,  nullptr, 3, 1);
    k_gemm_small<<<128, 256>>>(nullptr, 3, W2);  k_agg<<<1024, 256>>>(b2,  nullptr, 4, 1);
    k_gemm_small<<<128, 256>>>(nullptr, 4, Wmu); k_agg<<<1024, 256>>>(bmu, nullptr, 3, 0);
    k_gemm_small<<<128, 256>>>(nullptr, 3, W5);  k_agg<<<1024, 256>>>(b5,  nullptr, 4, 1);
    k_gemm_small<<<128, 256>>>(nullptr, 4, W6);  k_agg<<<1024, 256>>>(b6,  hout,    0, 1);

    // decoder: adj = s @ t^T on tensor cores (split-bf16, 3 products)
    k_decoder<<<dim3(64, 64), 256>>>(adj);
}

// round 7
// speedup vs baseline: 1.6999x; 1.1230x over previous
#include <cuda_runtime.h>
#include <cuda_bf16.h>
#include <cstdint>

#define N_NODES 8192
#define C_CH    128
#define N_EDGES 262144
#define KPACK   384            // 3 x 128 split-bf16 products folded into K

// ---------------- scratch (device globals; no allocation allowed) ----------------
__device__ __align__(16) float g_dis[N_NODES];
__device__ __align__(16) int   g_cnt[N_NODES];
__device__ __align__(16) int   g_off[N_NODES];
__device__ __align__(16) int   g_cur[N_NODES];
__device__ __align__(16) int2  g_csr[N_EDGES];
__device__ __align__(16) float g_h  [N_NODES * C_CH];
__device__ __align__(16) float g_s  [N_NODES * C_CH];
__device__ __align__(16) float g_t  [N_NODES * C_CH];
__device__ __align__(16) float g_u1 [N_NODES * C_CH];
__device__ __align__(16) float g_u2 [N_NODES * C_CH];
// packed split-bf16 decoder operands: A=[Sh|Sh|Sl], B=[Th|Tl|Th]
__device__ __align__(16) __nv_bfloat16 g_apack[N_NODES * KPACK];
__device__ __align__(16) __nv_bfloat16 g_bpack[N_NODES * KPACK];
__device__ int g_is64;

__device__ __forceinline__ float* buf_ptr(int s) {
    switch (s) {
        case 1: return g_s;
        case 2: return g_t;
        case 3: return g_u1;
        case 4: return g_u2;
        default: return g_h;
    }
}

// ---------------- edge_index dtype detection ----------------
__global__ void k_detect(const int* __restrict__ v) {
    __shared__ int any;
    if (threadIdx.x == 0) any = 0;
    __syncthreads();
    int acc = 0;
    for (int i = threadIdx.x; i < 8192; i += 256) {
        int idx = i * 64 + 1;
        acc |= v[idx];
    }
    if (acc) atomicOr(&any, 1);
    __syncthreads();
    if (threadIdx.x == 0) g_is64 = (any == 0) ? 1 : 0;
}

__device__ __forceinline__ int edge_at(const void* ei, int idx) {
    int v;
    if (g_is64) v = (int)((const long long*)ei)[idx];
    else        v = ((const int*)ei)[idx];
    return v & (N_NODES - 1);
}

// ---------------- graph preprocessing ----------------
__global__ void k_zero_cnt() {
    int i = blockIdx.x * blockDim.x + threadIdx.x;
    if (i < N_NODES) g_cnt[i] = 0;
}
__global__ void k_deg(const void* __restrict__ ei) {
    int e = blockIdx.x * blockDim.x + threadIdx.x;
    if (e < N_EDGES) atomicAdd(&g_cnt[edge_at(ei, N_EDGES + e)], 1);
}
__global__ void k_dis() {
    int i = blockIdx.x * blockDim.x + threadIdx.x;
    if (i < N_NODES) g_dis[i] = rsqrtf((float)g_cnt[i] + 1.0f);
}
__global__ void k_scan() {
    __shared__ int part[1024];
    int t = threadIdx.x;
    int base = t * 8;
    int loc[8];
    int s = 0;
#pragma unroll
    for (int i = 0; i < 8; i++) { loc[i] = g_cnt[base + i]; s += loc[i]; }
    part[t] = s;
    __syncthreads();
    for (int off = 1; off < 1024; off <<= 1) {
        int v = 0;
        if (t >= off) v = part[t - off];
        __syncthreads();
        part[t] += v;
        __syncthreads();
    }
    int run = part[t] - s;
#pragma unroll
    for (int i = 0; i < 8; i++) {
        g_off[base + i] = run;
        g_cur[base + i] = run;
        run += loc[i];
    }
}
__global__ void k_fill(const void* __restrict__ ei) {
    int e = blockIdx.x * blockDim.x + threadIdx.x;
    if (e < N_EDGES) {
        int s = edge_at(ei, e);
        int d = edge_at(ei, N_EDGES + e);
        float w = g_dis[s] * g_dis[d];
        int p = atomicAdd(&g_cur[d], 1);
        if (p < N_EDGES) g_csr[p] = make_int2(s, __float_as_int(w));
    }
}

// ---------------- dense GEMM: g_h = A @ W ----------------
__global__ __launch_bounds__(256) void k_gemm_small(const float* __restrict__ Aext,
                                                    int selA,
                                                    const float* __restrict__ W) {
    __shared__ float Wsm[32 * 128];
    __shared__ float Asm[64 * 40];

    const float* A = Aext ? Aext : buf_ptr(selA);
    int tid = threadIdx.x;
    int rb  = blockIdx.x * 64;
    int cg = tid & 15, rg = tid >> 4;
    int r0 = rg * 4, c0 = cg * 8;

    float acc[4][8];
#pragma unroll
    for (int i = 0; i < 4; i++)
#pragma unroll
        for (int j = 0; j < 8; j++) acc[i][j] = 0.f;

    for (int c = 0; c < 4; c++) {
        int kc0 = c * 32;
        __syncthreads();
#pragma unroll
        for (int i = 0; i < 4; i++) {
            int idx = tid + i * 256;
            int k = idx >> 5, c4 = idx & 31;
            *(float4*)&Wsm[k * 128 + c4 * 4] =
                *(const float4*)&W[(size_t)(kc0 + k) * 128 + c4 * 4];
        }
#pragma unroll
        for (int i = 0; i < 2; i++) {
            int idx = tid + i * 256;
            int row = idx >> 3, c4 = idx & 7;
            *(float4*)&Asm[row * 40 + c4 * 4] =
                *(const float4*)&A[(size_t)(rb + row) * 128 + kc0 + c4 * 4];
        }
        __syncthreads();

#pragma unroll
        for (int k = 0; k < 32; k += 4) {
            float4 a[4];
#pragma unroll
            for (int i = 0; i < 4; i++) a[i] = *(const float4*)&Asm[(r0 + i) * 40 + k];
#pragma unroll
            for (int kk = 0; kk < 4; kk++) {
                float4 bLo = *(const float4*)&Wsm[(k + kk) * 128 + c0];
                float4 bHi = *(const float4*)&Wsm[(k + kk) * 128 + c0 + 4];
                float bv[8] = {bLo.x, bLo.y, bLo.z, bLo.w, bHi.x, bHi.y, bHi.z, bHi.w};
#pragma unroll
                for (int i = 0; i < 4; i++) {
                    float av = (kk == 0) ? a[i].x : (kk == 1) ? a[i].y
                               : (kk == 2) ? a[i].z : a[i].w;
#pragma unroll
                    for (int j = 0; j < 8; j++)
                        acc[i][j] = fmaf(av, bv[j], acc[i][j]);
                }
            }
        }
    }

#pragma unroll
    for (int i = 0; i < 4; i++) {
        float4 lo = make_float4(acc[i][0], acc[i][1], acc[i][2], acc[i][3]);
        float4 hi = make_float4(acc[i][4], acc[i][5], acc[i][6], acc[i][7]);
        size_t base = (size_t)(rb + r0 + i) * 128 + c0;
        *(float4*)&g_h[base]     = lo;
        *(float4*)&g_h[base + 4] = hi;
    }
}

// ---------------- GCN aggregation ----------------
__global__ __launch_bounds__(256) void k_agg(const float* __restrict__ bias,
                                             float* __restrict__ Oext, int selO,
                                             int relu) {
    float* O = Oext ? Oext : buf_ptr(selO);
    int warp = threadIdx.x >> 5, lane = threadIdx.x & 31;
    int node = blockIdx.x * 8 + warp;
    const float4* H4 = (const float4*)g_h;

    float4 bb = ((const float4*)bias)[lane];
    float  di = g_dis[node];
    float  dd = di * di;
    float4 h  = H4[(size_t)node * 32 + lane];
    float4 acc;
    acc.x = fmaf(h.x, dd, bb.x);
    acc.y = fmaf(h.y, dd, bb.y);
    acc.z = fmaf(h.z, dd, bb.z);
    acc.w = fmaf(h.w, dd, bb.w);
    float4 acc2 = make_float4(0.f, 0.f, 0.f, 0.f);

    int start = g_off[node];
    int cnt   = g_cnt[node];
    int j = 0;
    for (; j + 1 < cnt; j += 2) {
        int2 e0 = g_csr[start + j];
        int2 e1 = g_csr[start + j + 1];
        float w0 = __int_as_float(e0.y);
        float w1 = __int_as_float(e1.y);
        float4 v0 = H4[(size_t)e0.x * 32 + lane];
        float4 v1 = H4[(size_t)e1.x * 32 + lane];
        acc.x  = fmaf(v0.x, w0, acc.x);  acc.y  = fmaf(v0.y, w0, acc.y);
        acc.z  = fmaf(v0.z, w0, acc.z);  acc.w  = fmaf(v0.w, w0, acc.w);
        acc2.x = fmaf(v1.x, w1, acc2.x); acc2.y = fmaf(v1.y, w1, acc2.y);
        acc2.z = fmaf(v1.z, w1, acc2.z); acc2.w = fmaf(v1.w, w1, acc2.w);
    }
    if (j < cnt) {
        int2 e0 = g_csr[start + j];
        float w0 = __int_as_float(e0.y);
        float4 v0 = H4[(size_t)e0.x * 32 + lane];
        acc.x = fmaf(v0.x, w0, acc.x); acc.y = fmaf(v0.y, w0, acc.y);
        acc.z = fmaf(v0.z, w0, acc.z); acc.w = fmaf(v0.w, w0, acc.w);
    }
    acc.x += acc2.x; acc.y += acc2.y; acc.z += acc2.z; acc.w += acc2.w;

    if (relu) {
        acc.x = fmaxf(acc.x, 0.f); acc.y = fmaxf(acc.y, 0.f);
        acc.z = fmaxf(acc.z, 0.f); acc.w = fmaxf(acc.w, 0.f);
    }
    ((float4*)O)[(size_t)node * 32 + lane] = acc;
}

// ---------------- split + pack: A=[Sh|Sh|Sl], B=[Th|Tl|Th] ----------------
__global__ __launch_bounds__(256) void k_split() {
    int i = blockIdx.x * blockDim.x + threadIdx.x;   // over N*C
    int row = i >> 7, c = i & 127;
    size_t b = (size_t)row * KPACK + c;

    float vs = g_s[i];
    __nv_bfloat16 sh = __float2bfloat16(vs);
    __nv_bfloat16 sl = __float2bfloat16(vs - __bfloat162float(sh));
    g_apack[b]       = sh;
    g_apack[b + 128] = sh;
    g_apack[b + 256] = sl;

    float vt = g_t[i];
    __nv_bfloat16 th = __float2bfloat16(vt);
    __nv_bfloat16 tl = __float2bfloat16(vt - __bfloat162float(th));
    g_bpack[b]       = th;
    g_bpack[b + 128] = tl;
    g_bpack[b + 256] = th;
}

// ---------------- HMMA decoder: adj = Apack @ Bpack^T ----------------
__device__ __forceinline__ void ldsm_x4(uint32_t& r0, uint32_t& r1,
                                        uint32_t& r2, uint32_t& r3, uint32_t a) {
    asm volatile("ldmatrix.sync.aligned.m8n8.x4.shared.b16 {%0,%1,%2,%3}, [%4];"
                 : "=r"(r0), "=r"(r1), "=r"(r2), "=r"(r3) : "r"(a));
}
__device__ __forceinline__ void mma_bf16(float& c0, float& c1, float& c2, float& c3,
                                         uint32_t a0, uint32_t a1, uint32_t a2, uint32_t a3,
                                         uint32_t b0, uint32_t b1) {
    asm volatile(
        "mma.sync.aligned.m16n8k16.row.col.f32.bf16.bf16.f32 "
        "{%0,%1,%2,%3}, {%4,%5,%6,%7}, {%8,%9}, {%0,%1,%2,%3};"
        : "+f"(c0), "+f"(c1), "+f"(c2), "+f"(c3)
        : "r"(a0), "r"(a1), "r"(a2), "r"(a3), "r"(b0), "r"(b1));
}
__device__ __forceinline__ void cp_async16(uint32_t dst, const void* src) {
    asm volatile("cp.async.cg.shared.global [%0], [%1], 16;" :: "r"(dst), "l"(src));
}
#define CP_COMMIT() asm volatile("cp.async.commit_group;" ::: "memory")
#define CP_WAIT(n)  asm volatile("cp.async.wait_group %0;" :: "n"(n) : "memory")
#define SWZ(off) ((off) ^ (((off) >> 3) & 0x70))

#define A_BYTES   32768        // 256 rows x 128B
#define B_BYTES   16384        // 128 rows x 128B
#define BUF_BYTES (A_BYTES + B_BYTES)
#define DEC_SMEM  (2 * BUF_BYTES)   // 96 KB

__global__ __launch_bounds__(256) void k_decoder(float* __restrict__ adj) {
    extern __shared__ __align__(16) char smem[];
    uint32_t sbase = (uint32_t)__cvta_generic_to_shared(smem);

    int tid  = threadIdx.x;
    int wid  = tid >> 5, lane = tid & 31;
    int wm   = wid >> 1, wn = wid & 1;        // 4 x 2 warp grid, warp tile m64 n64
    int cb   = blockIdx.x * 128;              // N offset
    int rb   = blockIdx.y * 256;              // M offset

    float acc[4][8][4];
#pragma unroll
    for (int m = 0; m < 4; m++)
#pragma unroll
        for (int n = 0; n < 8; n++)
#pragma unroll
            for (int r = 0; r < 4; r++) acc[m][n][r] = 0.f;

    // chunk c (Kc=64 bf16 = 128B rows) -> buffer buf
#define LOAD_CHUNK(c, buf) do {                                                  \
    int kc0 = (c) * 64;                                                          \
    uint32_t base = sbase + (buf) * BUF_BYTES;                                   \
    _Pragma("unroll")                                                            \
    for (int i = 0; i < 12; i++) {                                               \
        int seg = tid + i * 256;                                                 \
        if (seg < 2048) {                                                        \
            int row = seg >> 3, sgi = seg & 7;                                   \
            uint32_t off = (uint32_t)(row * 128 + sgi * 16);                     \
            cp_async16(base + SWZ(off),                                          \
                       &g_apack[(size_t)(rb + row) * KPACK + kc0 + sgi * 8]);    \
        } else {                                                                 \
            int bseg = seg - 2048;                                               \
            int row = bseg >> 3, sgi = bseg & 7;                                 \
            uint32_t off = (uint32_t)(row * 128 + sgi * 16);                     \
            cp_async16(base + A_BYTES + SWZ(off),                                \
                       &g_bpack[(size_t)(cb + row) * KPACK + kc0 + sgi * 8]);    \
        }                                                                        \
    }                                                                            \
} while (0)

    LOAD_CHUNK(0, 0);
    CP_COMMIT();

#pragma unroll 1
    for (int c = 0; c < 6; c++) {
        int buf = c & 1;
        if (c < 5) {
            LOAD_CHUNK(c + 1, buf ^ 1);
            CP_COMMIT();
            CP_WAIT(1);            // chunk c arrived; c+1 still in flight
        } else {
            CP_WAIT(0);
        }
        __syncthreads();

        uint32_t abase = sbase + buf * BUF_BYTES;
        uint32_t bbase = abase + A_BYTES;
#pragma unroll
        for (int ks = 0; ks < 4; ks++) {
            uint32_t a[4][4], b[4][4];
#pragma unroll
            for (int mt = 0; mt < 4; mt++) {
                int row = wm * 64 + mt * 16 + (lane & 15);
                uint32_t off = (uint32_t)(row * 128 + ks * 32 + ((lane >> 4) & 1) * 16);
                ldsm_x4(a[mt][0], a[mt][1], a[mt][2], a[mt][3], abase + SWZ(off));
            }
#pragma unroll
            for (int nt = 0; nt < 4; nt++) {
                int row = wn * 64 + nt * 16 + (lane & 15);
                uint32_t off = (uint32_t)(row * 128 + ks * 32 + ((lane >> 4) & 1) * 16);
                ldsm_x4(b[nt][0], b[nt][1], b[nt][2], b[nt][3], bbase + SWZ(off));
            }
#pragma unroll
            for (int mt = 0; mt < 4; mt++)
#pragma unroll
                for (int nt = 0; nt < 4; nt++) {
                    // n8 frag 0: B rows nt*16+0..7  -> regs {b0, b2}
                    mma_bf16(acc[mt][nt * 2][0], acc[mt][nt * 2][1],
                             acc[mt][nt * 2][2], acc[mt][nt * 2][3],
                             a[mt][0], a[mt][1], a[mt][2], a[mt][3],
                             b[nt][0], b[nt][2]);
                    // n8 frag 1: B rows nt*16+8..15 -> regs {b1, b3}
                    mma_bf16(acc[mt][nt * 2 + 1][0], acc[mt][nt * 2 + 1][1],
                             acc[mt][nt * 2 + 1][2], acc[mt][nt * 2 + 1][3],
                             a[mt][0], a[mt][1], a[mt][2], a[mt][3],
                             b[nt][1], b[nt][3]);
                }
        }
        __syncthreads();           // buffer free before next prefetch overwrites
    }

    // epilogue: frag rows lane>>2 (+8), cols (lane&3)*2
#pragma unroll
    for (int mt = 0; mt < 4; mt++) {
#pragma unroll
        for (int nt = 0; nt < 8; nt++) {
            int row = rb + wm * 64 + mt * 16 + (lane >> 2);
            int col = cb + wn * 64 + nt * 8 + (lane & 3) * 2;
            *(float2*)&adj[(size_t)row * 8192 + col] =
                make_float2(acc[mt][nt][0], acc[mt][nt][1]);
            *(float2*)&adj[(size_t)(row + 8) * 8192 + col] =
                make_float2(acc[mt][nt][2], acc[mt][nt][3]);
        }
    }
}

// ---------------- launch ----------------
extern "C" void kernel_launch(void* const* d_in, const int* in_sizes, int n_in,
                              void* d_out, int out_size) {
    (void)in_sizes; (void)n_in;
    const float* x  = (const float*)d_in[0];
    const void*  ei = d_in[1];
    const float *Ws = (const float*)d_in[2],  *bs  = (const float*)d_in[3];
    const float *Wt = (const float*)d_in[4],  *bt  = (const float*)d_in[5];
    const float *W1 = (const float*)d_in[6],  *b1  = (const float*)d_in[7];
    const float *W2 = (const float*)d_in[8],  *b2  = (const float*)d_in[9];
    const float *Wmu= (const float*)d_in[10], *bmu = (const float*)d_in[11];
    const float *W5 = (const float*)d_in[12], *b5  = (const float*)d_in[13];
    const float *W6 = (const float*)d_in[14], *b6  = (const float*)d_in[15];

    float* adj  = (float*)d_out;
    float* hout = (float*)d_out + ((size_t)out_size - (size_t)N_NODES * C_CH);

    cudaFuncSetAttribute(k_decoder, cudaFuncAttributeMaxDynamicSharedMemorySize,
                         DEC_SMEM);

    // graph preprocessing
    k_detect<<<1, 256>>>((const int*)ei);
    k_zero_cnt<<<N_NODES / 256, 256>>>();
    k_deg<<<N_EDGES / 256, 256>>>(ei);
    k_dis<<<N_NODES / 256, 256>>>();
    k_scan<<<1, 1024>>>();
    k_fill<<<N_EDGES / 256, 256>>>(ei);

    // GCN layers
    k_gemm_small<<<128, 256>>>(x,       0, Ws);  k_agg<<<1024, 256>>>(bs,  nullptr, 1, 0);
    k_gemm_small<<<128, 256>>>(x,       0, Wt);  k_agg<<<1024, 256>>>(bt,  nullptr, 2, 0);
    k_split<<<(N_NODES * C_CH) / 256, 256>>>();
    k_gemm_small<<<128, 256>>>(x,       0, W1);  k_agg<<<1024, 256>>>(b1,  nullptr, 3, 1);
    k_gemm_small<<<128, 256>>>(nullptr, 3, W2);  k_agg<<<1024, 256>>>(b2,  nullptr, 4, 1);
    k_gemm_small<<<128, 256>>>(nullptr, 4, Wmu); k_agg<<<1024, 256>>>(bmu, nullptr, 3, 0);
    k_gemm_small<<<128, 256>>>(nullptr, 3, W5);  k_agg<<<1024, 256>>>(b5,  nullptr, 4, 1);
    k_gemm_small<<<128, 256>>>(nullptr, 4, W6);  k_agg<<<1024, 256>>>(b6,  hout,    0, 1);

    // decoder: tensor-core HMMA, double-buffered
    k_decoder<<<dim3(64, 32), 256, DEC_SMEM>>>(adj);
}

// round 8
// speedup vs baseline: 1.8868x; 1.1100x over previous
#include <cuda_runtime.h>
#include <cuda_bf16.h>
#include <cstdint>

#define N_NODES 8192
#define C_CH    128
#define N_EDGES 262144
#define KPACK   384            // 3 x 128 split-bf16 products folded into K

// ---------------- scratch (device globals; no allocation allowed) ----------------
__device__ __align__(16) float g_dis[N_NODES];
__device__ __align__(16) int   g_cnt[N_NODES];
__device__ __align__(16) int   g_off[N_NODES];
__device__ __align__(16) int   g_cur[N_NODES];
__device__ __align__(16) int2  g_csr[N_EDGES];
__device__ __align__(16) float g_h  [N_NODES * C_CH];   // NodeModel-arm gemm scratch
__device__ __align__(16) float g_ha [N_NODES * C_CH];   // encoder-arm gemm scratch
__device__ __align__(16) float g_s  [N_NODES * C_CH];
__device__ __align__(16) float g_t  [N_NODES * C_CH];
__device__ __align__(16) float g_u1 [N_NODES * C_CH];
__device__ __align__(16) float g_u2 [N_NODES * C_CH];
// packed split-bf16 decoder operands: A=[Sh|Sh|Sl], B=[Th|Tl|Th]
__device__ __align__(16) __nv_bfloat16 g_apack[N_NODES * KPACK];
__device__ __align__(16) __nv_bfloat16 g_bpack[N_NODES * KPACK];
__device__ int g_is64;

__device__ __forceinline__ float* buf_ptr(int s) {
    switch (s) {
        case 1: return g_s;
        case 2: return g_t;
        case 3: return g_u1;
        case 4: return g_u2;
        case 5: return g_ha;
        default: return g_h;
    }
}

// ---------------- edge_index dtype detection ----------------
__global__ void k_detect(const int* __restrict__ v) {
    __shared__ int any;
    if (threadIdx.x == 0) any = 0;
    __syncthreads();
    int acc = 0;
    for (int i = threadIdx.x; i < 8192; i += 256) {
        int idx = i * 64 + 1;
        acc |= v[idx];
    }
    if (acc) atomicOr(&any, 1);
    __syncthreads();
    if (threadIdx.x == 0) g_is64 = (any == 0) ? 1 : 0;
}

__device__ __forceinline__ int edge_at(const void* ei, int idx) {
    int v;
    if (g_is64) v = (int)((const long long*)ei)[idx];
    else        v = ((const int*)ei)[idx];
    return v & (N_NODES - 1);
}

// ---------------- graph preprocessing ----------------
__global__ void k_zero_cnt() {
    int i = blockIdx.x * blockDim.x + threadIdx.x;
    if (i < N_NODES) g_cnt[i] = 0;
}
__global__ void k_deg(const void* __restrict__ ei) {
    int e = blockIdx.x * blockDim.x + threadIdx.x;
    if (e < N_EDGES) atomicAdd(&g_cnt[edge_at(ei, N_EDGES + e)], 1);
}
__global__ void k_dis() {
    int i = blockIdx.x * blockDim.x + threadIdx.x;
    if (i < N_NODES) g_dis[i] = rsqrtf((float)g_cnt[i] + 1.0f);
}
__global__ void k_scan() {
    __shared__ int part[1024];
    int t = threadIdx.x;
    int base = t * 8;
    int loc[8];
    int s = 0;
#pragma unroll
    for (int i = 0; i < 8; i++) { loc[i] = g_cnt[base + i]; s += loc[i]; }
    part[t] = s;
    __syncthreads();
    for (int off = 1; off < 1024; off <<= 1) {
        int v = 0;
        if (t >= off) v = part[t - off];
        __syncthreads();
        part[t] += v;
        __syncthreads();
    }
    int run = part[t] - s;
#pragma unroll
    for (int i = 0; i < 8; i++) {
        g_off[base + i] = run;
        g_cur[base + i] = run;
        run += loc[i];
    }
}
__global__ void k_fill(const void* __restrict__ ei) {
    int e = blockIdx.x * blockDim.x + threadIdx.x;
    if (e < N_EDGES) {
        int s = edge_at(ei, e);
        int d = edge_at(ei, N_EDGES + e);
        float w = g_dis[s] * g_dis[d];
        int p = atomicAdd(&g_cur[d], 1);
        if (p < N_EDGES) g_csr[p] = make_int2(s, __float_as_int(w));
    }
}

// ---------------- dense GEMM: buf_ptr(outSel) = A @ W ----------------
__global__ __launch_bounds__(256) void k_gemm_small(const float* __restrict__ Aext,
                                                    int selA,
                                                    const float* __restrict__ W,
                                                    int outSel) {
    __shared__ float Wsm[32 * 128];
    __shared__ float Asm[64 * 40];

    const float* A = Aext ? Aext : buf_ptr(selA);
    float* Ob = buf_ptr(outSel);
    int tid = threadIdx.x;
    int rb  = blockIdx.x * 64;
    int cg = tid & 15, rg = tid >> 4;
    int r0 = rg * 4, c0 = cg * 8;

    float acc[4][8];
#pragma unroll
    for (int i = 0; i < 4; i++)
#pragma unroll
        for (int j = 0; j < 8; j++) acc[i][j] = 0.f;

    for (int c = 0; c < 4; c++) {
        int kc0 = c * 32;
        __syncthreads();
#pragma unroll
        for (int i = 0; i < 4; i++) {
            int idx = tid + i * 256;
            int k = idx >> 5, c4 = idx & 31;
            *(float4*)&Wsm[k * 128 + c4 * 4] =
                *(const float4*)&W[(size_t)(kc0 + k) * 128 + c4 * 4];
        }
#pragma unroll
        for (int i = 0; i < 2; i++) {
            int idx = tid + i * 256;
            int row = idx >> 3, c4 = idx & 7;
            *(float4*)&Asm[row * 40 + c4 * 4] =
                *(const float4*)&A[(size_t)(rb + row) * 128 + kc0 + c4 * 4];
        }
        __syncthreads();

#pragma unroll
        for (int k = 0; k < 32; k += 4) {
            float4 a[4];
#pragma unroll
            for (int i = 0; i < 4; i++) a[i] = *(const float4*)&Asm[(r0 + i) * 40 + k];
#pragma unroll
            for (int kk = 0; kk < 4; kk++) {
                float4 bLo = *(const float4*)&Wsm[(k + kk) * 128 + c0];
                float4 bHi = *(const float4*)&Wsm[(k + kk) * 128 + c0 + 4];
                float bv[8] = {bLo.x, bLo.y, bLo.z, bLo.w, bHi.x, bHi.y, bHi.z, bHi.w};
#pragma unroll
                for (int i = 0; i < 4; i++) {
                    float av = (kk == 0) ? a[i].x : (kk == 1) ? a[i].y
                               : (kk == 2) ? a[i].z : a[i].w;
#pragma unroll
                    for (int j = 0; j < 8; j++)
                        acc[i][j] = fmaf(av, bv[j], acc[i][j]);
                }
            }
        }
    }

#pragma unroll
    for (int i = 0; i < 4; i++) {
        float4 lo = make_float4(acc[i][0], acc[i][1], acc[i][2], acc[i][3]);
        float4 hi = make_float4(acc[i][4], acc[i][5], acc[i][6], acc[i][7]);
        size_t base = (size_t)(rb + r0 + i) * 128 + c0;
        *(float4*)&Ob[base]     = lo;
        *(float4*)&Ob[base + 4] = hi;
    }
}

// ---------------- GCN aggregation: reads buf_ptr(inSel) ----------------
__global__ __launch_bounds__(256) void k_agg(const float* __restrict__ bias,
                                             float* __restrict__ Oext, int selO,
                                             int relu, int inSel) {
    float* O = Oext ? Oext : buf_ptr(selO);
    const float4* H4 = (const float4*)buf_ptr(inSel);
    int warp = threadIdx.x >> 5, lane = threadIdx.x & 31;
    int node = blockIdx.x * 8 + warp;

    float4 bb = ((const float4*)bias)[lane];
    float  di = g_dis[node];
    float  dd = di * di;
    float4 h  = H4[(size_t)node * 32 + lane];
    float4 acc;
    acc.x = fmaf(h.x, dd, bb.x);
    acc.y = fmaf(h.y, dd, bb.y);
    acc.z = fmaf(h.z, dd, bb.z);
    acc.w = fmaf(h.w, dd, bb.w);
    float4 acc2 = make_float4(0.f, 0.f, 0.f, 0.f);

    int start = g_off[node];
    int cnt   = g_cnt[node];
    int j = 0;
    for (; j + 1 < cnt; j += 2) {
        int2 e0 = g_csr[start + j];
        int2 e1 = g_csr[start + j + 1];
        float w0 = __int_as_float(e0.y);
        float w1 = __int_as_float(e1.y);
        float4 v0 = H4[(size_t)e0.x * 32 + lane];
        float4 v1 = H4[(size_t)e1.x * 32 + lane];
        acc.x  = fmaf(v0.x, w0, acc.x);  acc.y  = fmaf(v0.y, w0, acc.y);
        acc.z  = fmaf(v0.z, w0, acc.z);  acc.w  = fmaf(v0.w, w0, acc.w);
        acc2.x = fmaf(v1.x, w1, acc2.x); acc2.y = fmaf(v1.y, w1, acc2.y);
        acc2.z = fmaf(v1.z, w1, acc2.z); acc2.w = fmaf(v1.w, w1, acc2.w);
    }
    if (j < cnt) {
        int2 e0 = g_csr[start + j];
        float w0 = __int_as_float(e0.y);
        float4 v0 = H4[(size_t)e0.x * 32 + lane];
        acc.x = fmaf(v0.x, w0, acc.x); acc.y = fmaf(v0.y, w0, acc.y);
        acc.z = fmaf(v0.z, w0, acc.z); acc.w = fmaf(v0.w, w0, acc.w);
    }
    acc.x += acc2.x; acc.y += acc2.y; acc.z += acc2.z; acc.w += acc2.w;

    if (relu) {
        acc.x = fmaxf(acc.x, 0.f); acc.y = fmaxf(acc.y, 0.f);
        acc.z = fmaxf(acc.z, 0.f); acc.w = fmaxf(acc.w, 0.f);
    }
    ((float4*)O)[(size_t)node * 32 + lane] = acc;
}

// ---------------- split + pack: A=[Sh|Sh|Sl], B=[Th|Tl|Th] ----------------
__global__ __launch_bounds__(256) void k_split() {
    int i = blockIdx.x * blockDim.x + threadIdx.x;   // over N*C
    int row = i >> 7, c = i & 127;
    size_t b = (size_t)row * KPACK + c;

    float vs = g_s[i];
    __nv_bfloat16 sh = __float2bfloat16(vs);
    __nv_bfloat16 sl = __float2bfloat16(vs - __bfloat162float(sh));
    g_apack[b]       = sh;
    g_apack[b + 128] = sh;
    g_apack[b + 256] = sl;

    float vt = g_t[i];
    __nv_bfloat16 th = __float2bfloat16(vt);
    __nv_bfloat16 tl = __float2bfloat16(vt - __bfloat162float(th));
    g_bpack[b]       = th;
    g_bpack[b + 128] = tl;
    g_bpack[b + 256] = th;
}

// ---------------- HMMA decoder: adj = Apack @ Bpack^T ----------------
__device__ __forceinline__ void ldsm_x4(uint32_t& r0, uint32_t& r1,
                                        uint32_t& r2, uint32_t& r3, uint32_t a) {
    asm volatile("ldmatrix.sync.aligned.m8n8.x4.shared.b16 {%0,%1,%2,%3}, [%4];"
                 : "=r"(r0), "=r"(r1), "=r"(r2), "=r"(r3) : "r"(a));
}
__device__ __forceinline__ void mma_bf16(float& c0, float& c1, float& c2, float& c3,
                                         uint32_t a0, uint32_t a1, uint32_t a2, uint32_t a3,
                                         uint32_t b0, uint32_t b1) {
    asm volatile(
        "mma.sync.aligned.m16n8k16.row.col.f32.bf16.bf16.f32 "
        "{%0,%1,%2,%3}, {%4,%5,%6,%7}, {%8,%9}, {%0,%1,%2,%3};"
        : "+f"(c0), "+f"(c1), "+f"(c2), "+f"(c3)
        : "r"(a0), "r"(a1), "r"(a2), "r"(a3), "r"(b0), "r"(b1));
}
__device__ __forceinline__ void cp_async16(uint32_t dst, const void* src) {
    asm volatile("cp.async.cg.shared.global [%0], [%1], 16;" :: "r"(dst), "l"(src));
}
#define CP_COMMIT() asm volatile("cp.async.commit_group;" ::: "memory")
#define CP_WAIT(n)  asm volatile("cp.async.wait_group %0;" :: "n"(n) : "memory")
#define SWZ(off) ((off) ^ (((off) >> 3) & 0x70))

#define A_BYTES   32768        // 256 rows x 128B
#define B_BYTES   16384        // 128 rows x 128B
#define BUF_BYTES (A_BYTES + B_BYTES)
#define DEC_SMEM  (2 * BUF_BYTES)   // 96 KB

__global__ __launch_bounds__(256) void k_decoder(float* __restrict__ adj) {
    extern __shared__ __align__(16) char smem[];
    uint32_t sbase = (uint32_t)__cvta_generic_to_shared(smem);

    int tid  = threadIdx.x;
    int wid  = tid >> 5, lane = tid & 31;
    int wm   = wid >> 1, wn = wid & 1;        // 4 x 2 warp grid, warp tile m64 n64
    int cb   = blockIdx.x * 128;              // N offset
    int rb   = blockIdx.y * 256;              // M offset

    float acc[4][8][4];
#pragma unroll
    for (int m = 0; m < 4; m++)
#pragma unroll
        for (int n = 0; n < 8; n++)
#pragma unroll
            for (int r = 0; r < 4; r++) acc[m][n][r] = 0.f;

#define LOAD_CHUNK(c, buf) do {                                                  \
    int kc0 = (c) * 64;                                                          \
    uint32_t base = sbase + (buf) * BUF_BYTES;                                   \
    _Pragma("unroll")                                                            \
    for (int i = 0; i < 12; i++) {                                               \
        int seg = tid + i * 256;                                                 \
        if (seg < 2048) {                                                        \
            int row = seg >> 3, sgi = seg & 7;                                   \
            uint32_t off = (uint32_t)(row * 128 + sgi * 16);                     \
            cp_async16(base + SWZ(off),                                          \
                       &g_apack[(size_t)(rb + row) * KPACK + kc0 + sgi * 8]);    \
        } else {                                                                 \
            int bseg = seg - 2048;                                               \
            int row = bseg >> 3, sgi = bseg & 7;                                 \
            uint32_t off = (uint32_t)(row * 128 + sgi * 16);                     \
            cp_async16(base + A_BYTES + SWZ(off),                                \
                       &g_bpack[(size_t)(cb + row) * KPACK + kc0 + sgi * 8]);    \
        }                                                                        \
    }                                                                            \
} while (0)

    LOAD_CHUNK(0, 0);
    CP_COMMIT();

#pragma unroll 1
    for (int c = 0; c < 6; c++) {
        int buf = c & 1;
        if (c < 5) {
            LOAD_CHUNK(c + 1, buf ^ 1);
            CP_COMMIT();
            CP_WAIT(1);
        } else {
            CP_WAIT(0);
        }
        __syncthreads();

        uint32_t abase = sbase + buf * BUF_BYTES;
        uint32_t bbase = abase + A_BYTES;
#pragma unroll
        for (int ks = 0; ks < 4; ks++) {
            uint32_t a[4][4], b[4][4];
#pragma unroll
            for (int mt = 0; mt < 4; mt++) {
                int row = wm * 64 + mt * 16 + (lane & 15);
                uint32_t off = (uint32_t)(row * 128 + ks * 32 + ((lane >> 4) & 1) * 16);
                ldsm_x4(a[mt][0], a[mt][1], a[mt][2], a[mt][3], abase + SWZ(off));
            }
#pragma unroll
            for (int nt = 0; nt < 4; nt++) {
                int row = wn * 64 + nt * 16 + (lane & 15);
                uint32_t off = (uint32_t)(row * 128 + ks * 32 + ((lane >> 4) & 1) * 16);
                ldsm_x4(b[nt][0], b[nt][1], b[nt][2], b[nt][3], bbase + SWZ(off));
            }
#pragma unroll
            for (int mt = 0; mt < 4; mt++)
#pragma unroll
                for (int nt = 0; nt < 4; nt++) {
                    mma_bf16(acc[mt][nt * 2][0], acc[mt][nt * 2][1],
                             acc[mt][nt * 2][2], acc[mt][nt * 2][3],
                             a[mt][0], a[mt][1], a[mt][2], a[mt][3],
                             b[nt][0], b[nt][2]);
                    mma_bf16(acc[mt][nt * 2 + 1][0], acc[mt][nt * 2 + 1][1],
                             acc[mt][nt * 2 + 1][2], acc[mt][nt * 2 + 1][3],
                             a[mt][0], a[mt][1], a[mt][2], a[mt][3],
                             b[nt][1], b[nt][3]);
                }
        }
        __syncthreads();
    }

#pragma unroll
    for (int mt = 0; mt < 4; mt++) {
#pragma unroll
        for (int nt = 0; nt < 8; nt++) {
            int row = rb + wm * 64 + mt * 16 + (lane >> 2);
            int col = cb + wn * 64 + nt * 8 + (lane & 3) * 2;
            *(float2*)&adj[(size_t)row * 8192 + col] =
                make_float2(acc[mt][nt][0], acc[mt][nt][1]);
            *(float2*)&adj[(size_t)(row + 8) * 8192 + col] =
                make_float2(acc[mt][nt][2], acc[mt][nt][3]);
        }
    }
}

// ---------------- launch: forked-capture two-arm schedule ----------------
extern "C" void kernel_launch(void* const* d_in, const int* in_sizes, int n_in,
                              void* d_out, int out_size) {
    (void)in_sizes; (void)n_in;
    const float* x  = (const float*)d_in[0];
    const void*  ei = d_in[1];
    const float *Ws = (const float*)d_in[2],  *bs  = (const float*)d_in[3];
    const float *Wt = (const float*)d_in[4],  *bt  = (const float*)d_in[5];
    const float *W1 = (const float*)d_in[6],  *b1  = (const float*)d_in[7];
    const float *W2 = (const float*)d_in[8],  *b2  = (const float*)d_in[9];
    const float *Wmu= (const float*)d_in[10], *bmu = (const float*)d_in[11];
    const float *W5 = (const float*)d_in[12], *b5  = (const float*)d_in[13];
    const float *W6 = (const float*)d_in[14], *b6  = (const float*)d_in[15];

    float* adj  = (float*)d_out;
    float* hout = (float*)d_out + ((size_t)out_size - (size_t)N_NODES * C_CH);

    cudaFuncSetAttribute(k_decoder, cudaFuncAttributeMaxDynamicSharedMemorySize,
                         DEC_SMEM);

    cudaStream_t sB;
    cudaStreamCreateWithFlags(&sB, cudaStreamNonBlocking);
    cudaEvent_t evStart, evPre, evB;
    cudaEventCreateWithFlags(&evStart, cudaEventDisableTiming);
    cudaEventCreateWithFlags(&evPre,   cudaEventDisableTiming);
    cudaEventCreateWithFlags(&evB,     cudaEventDisableTiming);

    // ---- fork anchor ----
    cudaEventRecord(evStart, 0);
    cudaStreamWaitEvent(sB, evStart, 0);

    // ---- arm B (side stream): first NodeModel gemm needs only x ----
    k_gemm_small<<<128, 256, 0, sB>>>(x, 0, W1, 0);

    // ---- main stream: graph preprocessing ----
    k_detect<<<1, 256>>>((const int*)ei);
    k_zero_cnt<<<N_NODES / 256, 256>>>();
    k_deg<<<N_EDGES / 256, 256>>>(ei);
    k_dis<<<N_NODES / 256, 256>>>();
    k_scan<<<1, 1024>>>();
    k_fill<<<N_EDGES / 256, 256>>>(ei);
    cudaEventRecord(evPre, 0);

    // ---- arm B continues after preprocessing: NodeModel chain ----
    cudaStreamWaitEvent(sB, evPre, 0);
    k_agg<<<1024, 256, 0, sB>>>(b1,  nullptr, 3, 1, 0);
    k_gemm_small<<<128, 256, 0, sB>>>(nullptr, 3, W2, 0);
    k_agg<<<1024, 256, 0, sB>>>(b2,  nullptr, 4, 1, 0);
    k_gemm_small<<<128, 256, 0, sB>>>(nullptr, 4, Wmu, 0);
    k_agg<<<1024, 256, 0, sB>>>(bmu, nullptr, 3, 0, 0);
    k_gemm_small<<<128, 256, 0, sB>>>(nullptr, 3, W5, 0);
    k_agg<<<1024, 256, 0, sB>>>(b5,  nullptr, 4, 1, 0);
    k_gemm_small<<<128, 256, 0, sB>>>(nullptr, 4, W6, 0);
    k_agg<<<1024, 256, 0, sB>>>(b6,  hout,    0, 1, 0);
    cudaEventRecord(evB, sB);

    // ---- arm A (main stream): encoder layers -> split -> decoder ----
    k_gemm_small<<<128, 256>>>(x, 0, Ws, 5);
    k_agg<<<1024, 256>>>(bs, nullptr, 1, 0, 5);
    k_gemm_small<<<128, 256>>>(x, 0, Wt, 5);
    k_agg<<<1024, 256>>>(bt, nullptr, 2, 0, 5);
    k_split<<<(N_NODES * C_CH) / 256, 256>>>();
    k_decoder<<<dim3(64, 32), 256, DEC_SMEM>>>(adj);

    // ---- join ----
    cudaStreamWaitEvent(0, evB, 0);
}

// round 9
// speedup vs baseline: 2.1292x; 1.1285x over previous
#include <cuda_runtime.h>
#include <cuda_fp16.h>
#include <cstdint>

#define N_NODES 8192
#define C_CH    128
#define N_EDGES 262144
#define KPACK   256            // 2 x 128 fp16-split products folded into K

// ---------------- scratch (device globals; no allocation allowed) ----------------
__device__ __align__(16) float g_dis[N_NODES];
__device__ __align__(16) int   g_cnt[N_NODES];
__device__ __align__(16) int   g_off[N_NODES];
__device__ __align__(16) int   g_cur[N_NODES];
__device__ __align__(16) int2  g_csr[N_EDGES];
__device__ __align__(16) float g_h  [N_NODES * C_CH];   // NodeModel-arm gemm scratch
__device__ __align__(16) float g_ha [N_NODES * C_CH];   // encoder-arm gemm scratch
__device__ __align__(16) float g_s  [N_NODES * C_CH];
__device__ __align__(16) float g_t  [N_NODES * C_CH];
__device__ __align__(16) float g_u1 [N_NODES * C_CH];
__device__ __align__(16) float g_u2 [N_NODES * C_CH];
// packed fp16 decoder operands: A=[Sh|Sl], B=[Th|Th]
__device__ __align__(16) __half g_apack[N_NODES * KPACK];
__device__ __align__(16) __half g_bpack[N_NODES * KPACK];
__device__ int g_is64;

__device__ __forceinline__ float* buf_ptr(int s) {
    switch (s) {
        case 1: return g_s;
        case 2: return g_t;
        case 3: return g_u1;
        case 4: return g_u2;
        case 5: return g_ha;
        default: return g_h;
    }
}

// ---------------- edge_index dtype detection ----------------
__global__ void k_detect(const int* __restrict__ v) {
    __shared__ int any;
    if (threadIdx.x == 0) any = 0;
    __syncthreads();
    int acc = 0;
    for (int i = threadIdx.x; i < 8192; i += 256) {
        int idx = i * 64 + 1;
        acc |= v[idx];
    }
    if (acc) atomicOr(&any, 1);
    __syncthreads();
    if (threadIdx.x == 0) g_is64 = (any == 0) ? 1 : 0;
}

__device__ __forceinline__ int edge_at(const void* ei, int idx) {
    int v;
    if (g_is64) v = (int)((const long long*)ei)[idx];
    else        v = ((const int*)ei)[idx];
    return v & (N_NODES - 1);
}

// ---------------- graph preprocessing ----------------
__global__ void k_zero_cnt() {
    int i = blockIdx.x * blockDim.x + threadIdx.x;
    if (i < N_NODES) g_cnt[i] = 0;
}
__global__ void k_deg(const void* __restrict__ ei) {
    int e = blockIdx.x * blockDim.x + threadIdx.x;
    if (e < N_EDGES) atomicAdd(&g_cnt[edge_at(ei, N_EDGES + e)], 1);
}
__global__ void k_dis() {
    int i = blockIdx.x * blockDim.x + threadIdx.x;
    if (i < N_NODES) g_dis[i] = rsqrtf((float)g_cnt[i] + 1.0f);
}
__global__ void k_scan() {
    __shared__ int part[1024];
    int t = threadIdx.x;
    int base = t * 8;
    int loc[8];
    int s = 0;
#pragma unroll
    for (int i = 0; i < 8; i++) { loc[i] = g_cnt[base + i]; s += loc[i]; }
    part[t] = s;
    __syncthreads();
    for (int off = 1; off < 1024; off <<= 1) {
        int v = 0;
        if (t >= off) v = part[t - off];
        __syncthreads();
        part[t] += v;
        __syncthreads();
    }
    int run = part[t] - s;
#pragma unroll
    for (int i = 0; i < 8; i++) {
        g_off[base + i] = run;
        g_cur[base + i] = run;
        run += loc[i];
    }
}
__global__ void k_fill(const void* __restrict__ ei) {
    int e = blockIdx.x * blockDim.x + threadIdx.x;
    if (e < N_EDGES) {
        int s = edge_at(ei, e);
        int d = edge_at(ei, N_EDGES + e);
        float w = g_dis[s] * g_dis[d];
        int p = atomicAdd(&g_cur[d], 1);
        if (p < N_EDGES) g_csr[p] = make_int2(s, __float_as_int(w));
    }
}

// ---------------- dense GEMM: buf_ptr(outSel) = A @ W ----------------
__global__ __launch_bounds__(256) void k_gemm_small(const float* __restrict__ Aext,
                                                    int selA,
                                                    const float* __restrict__ W,
                                                    int outSel) {
    __shared__ float Wsm[32 * 128];
    __shared__ float Asm[64 * 40];

    const float* A = Aext ? Aext : buf_ptr(selA);
    float* Ob = buf_ptr(outSel);
    int tid = threadIdx.x;
    int rb  = blockIdx.x * 64;
    int cg = tid & 15, rg = tid >> 4;
    int r0 = rg * 4, c0 = cg * 8;

    float acc[4][8];
#pragma unroll
    for (int i = 0; i < 4; i++)
#pragma unroll
        for (int j = 0; j < 8; j++) acc[i][j] = 0.f;

    for (int c = 0; c < 4; c++) {
        int kc0 = c * 32;
        __syncthreads();
#pragma unroll
        for (int i = 0; i < 4; i++) {
            int idx = tid + i * 256;
            int k = idx >> 5, c4 = idx & 31;
            *(float4*)&Wsm[k * 128 + c4 * 4] =
                *(const float4*)&W[(size_t)(kc0 + k) * 128 + c4 * 4];
        }
#pragma unroll
        for (int i = 0; i < 2; i++) {
            int idx = tid + i * 256;
            int row = idx >> 3, c4 = idx & 7;
            *(float4*)&Asm[row * 40 + c4 * 4] =
                *(const float4*)&A[(size_t)(rb + row) * 128 + kc0 + c4 * 4];
        }
        __syncthreads();

#pragma unroll
        for (int k = 0; k < 32; k += 4) {
            float4 a[4];
#pragma unroll
            for (int i = 0; i < 4; i++) a[i] = *(const float4*)&Asm[(r0 + i) * 40 + k];
#pragma unroll
            for (int kk = 0; kk < 4; kk++) {
                float4 bLo = *(const float4*)&Wsm[(k + kk) * 128 + c0];
                float4 bHi = *(const float4*)&Wsm[(k + kk) * 128 + c0 + 4];
                float bv[8] = {bLo.x, bLo.y, bLo.z, bLo.w, bHi.x, bHi.y, bHi.z, bHi.w};
#pragma unroll
                for (int i = 0; i < 4; i++) {
                    float av = (kk == 0) ? a[i].x : (kk == 1) ? a[i].y
                               : (kk == 2) ? a[i].z : a[i].w;
#pragma unroll
                    for (int j = 0; j < 8; j++)
                        acc[i][j] = fmaf(av, bv[j], acc[i][j]);
                }
            }
        }
    }

#pragma unroll
    for (int i = 0; i < 4; i++) {
        float4 lo = make_float4(acc[i][0], acc[i][1], acc[i][2], acc[i][3]);
        float4 hi = make_float4(acc[i][4], acc[i][5], acc[i][6], acc[i][7]);
        size_t base = (size_t)(rb + r0 + i) * 128 + c0;
        *(float4*)&Ob[base]     = lo;
        *(float4*)&Ob[base + 4] = hi;
    }
}

// ---------------- GCN aggregation: reads buf_ptr(inSel) ----------------
__global__ __launch_bounds__(256) void k_agg(const float* __restrict__ bias,
                                             float* __restrict__ Oext, int selO,
                                             int relu, int inSel) {
    float* O = Oext ? Oext : buf_ptr(selO);
    const float4* H4 = (const float4*)buf_ptr(inSel);
    int warp = threadIdx.x >> 5, lane = threadIdx.x & 31;
    int node = blockIdx.x * 8 + warp;

    float4 bb = ((const float4*)bias)[lane];
    float  di = g_dis[node];
    float  dd = di * di;
    float4 h  = H4[(size_t)node * 32 + lane];
    float4 acc;
    acc.x = fmaf(h.x, dd, bb.x);
    acc.y = fmaf(h.y, dd, bb.y);
    acc.z = fmaf(h.z, dd, bb.z);
    acc.w = fmaf(h.w, dd, bb.w);
    float4 acc2 = make_float4(0.f, 0.f, 0.f, 0.f);

    int start = g_off[node];
    int cnt   = g_cnt[node];
    int j = 0;
    for (; j + 1 < cnt; j += 2) {
        int2 e0 = g_csr[start + j];
        int2 e1 = g_csr[start + j + 1];
        float w0 = __int_as_float(e0.y);
        float w1 = __int_as_float(e1.y);
        float4 v0 = H4[(size_t)e0.x * 32 + lane];
        float4 v1 = H4[(size_t)e1.x * 32 + lane];
        acc.x  = fmaf(v0.x, w0, acc.x);  acc.y  = fmaf(v0.y, w0, acc.y);
        acc.z  = fmaf(v0.z, w0, acc.z);  acc.w  = fmaf(v0.w, w0, acc.w);
        acc2.x = fmaf(v1.x, w1, acc2.x); acc2.y = fmaf(v1.y, w1, acc2.y);
        acc2.z = fmaf(v1.z, w1, acc2.z); acc2.w = fmaf(v1.w, w1, acc2.w);
    }
    if (j < cnt) {
        int2 e0 = g_csr[start + j];
        float w0 = __int_as_float(e0.y);
        float4 v0 = H4[(size_t)e0.x * 32 + lane];
        acc.x = fmaf(v0.x, w0, acc.x); acc.y = fmaf(v0.y, w0, acc.y);
        acc.z = fmaf(v0.z, w0, acc.z); acc.w = fmaf(v0.w, w0, acc.w);
    }
    acc.x += acc2.x; acc.y += acc2.y; acc.z += acc2.z; acc.w += acc2.w;

    if (relu) {
        acc.x = fmaxf(acc.x, 0.f); acc.y = fmaxf(acc.y, 0.f);
        acc.z = fmaxf(acc.z, 0.f); acc.w = fmaxf(acc.w, 0.f);
    }
    ((float4*)O)[(size_t)node * 32 + lane] = acc;
}

// ---------------- split + pack (fp16): A=[Sh|Sl], B=[Th|Th] ----------------
// adj = (Sh+Sl) @ Th^T = S @ Th^T ; dropped term S @ (T-Th)^T ~ 2^-12 RMS
__global__ __launch_bounds__(256) void k_split() {
    int i = blockIdx.x * blockDim.x + threadIdx.x;   // over N*C
    int row = i >> 7, c = i & 127;
    size_t b = (size_t)row * KPACK + c;

    float vs = g_s[i];
    __half sh = __float2half_rn(vs);
    __half sl = __float2half_rn(vs - __half2float(sh));
    g_apack[b]       = sh;
    g_apack[b + 128] = sl;

    __half th = __float2half_rn(g_t[i]);
    g_bpack[b]       = th;
    g_bpack[b + 128] = th;
}

// ---------------- HMMA decoder: adj = Apack @ Bpack^T (fp16, K=256) ----------------
__device__ __forceinline__ void ldsm_x4(uint32_t& r0, uint32_t& r1,
                                        uint32_t& r2, uint32_t& r3, uint32_t a) {
    asm volatile("ldmatrix.sync.aligned.m8n8.x4.shared.b16 {%0,%1,%2,%3}, [%4];"
                 : "=r"(r0), "=r"(r1), "=r"(r2), "=r"(r3) : "r"(a));
}
__device__ __forceinline__ void mma_f16(float& c0, float& c1, float& c2, float& c3,
                                        uint32_t a0, uint32_t a1, uint32_t a2, uint32_t a3,
                                        uint32_t b0, uint32_t b1) {
    asm volatile(
        "mma.sync.aligned.m16n8k16.row.col.f32.f16.f16.f32 "
        "{%0,%1,%2,%3}, {%4,%5,%6,%7}, {%8,%9}, {%0,%1,%2,%3};"
        : "+f"(c0), "+f"(c1), "+f"(c2), "+f"(c3)
        : "r"(a0), "r"(a1), "r"(a2), "r"(a3), "r"(b0), "r"(b1));
}
__device__ __forceinline__ void cp_async16(uint32_t dst, const void* src) {
    asm volatile("cp.async.cg.shared.global [%0], [%1], 16;" :: "r"(dst), "l"(src));
}
#define CP_COMMIT() asm volatile("cp.async.commit_group;" ::: "memory")
#define CP_WAIT(n)  asm volatile("cp.async.wait_group %0;" :: "n"(n) : "memory")
#define SWZ(off) ((off) ^ (((off) >> 3) & 0x70))

#define A_BYTES   32768        // 256 rows x 128B
#define B_BYTES   16384        // 128 rows x 128B
#define BUF_BYTES (A_BYTES + B_BYTES)
#define DEC_SMEM  (2 * BUF_BYTES)   // 96 KB

__global__ __launch_bounds__(256) void k_decoder(float* __restrict__ adj) {
    extern __shared__ __align__(16) char smem[];
    uint32_t sbase = (uint32_t)__cvta_generic_to_shared(smem);

    int tid  = threadIdx.x;
    int wid  = tid >> 5, lane = tid & 31;
    int wm   = wid >> 1, wn = wid & 1;        // 4 x 2 warp grid, warp tile m64 n64
    int cb   = blockIdx.x * 128;              // N offset
    int rb   = blockIdx.y * 256;              // M offset

    float acc[4][8][4];
#pragma unroll
    for (int m = 0; m < 4; m++)
#pragma unroll
        for (int n = 0; n < 8; n++)
#pragma unroll
            for (int r = 0; r < 4; r++) acc[m][n][r] = 0.f;

#define LOAD_CHUNK(c, buf) do {                                                  \
    int kc0 = (c) * 64;                                                          \
    uint32_t base = sbase + (buf) * BUF_BYTES;                                   \
    _Pragma("unroll")                                                            \
    for (int i = 0; i < 12; i++) {                                               \
        int seg = tid + i * 256;                                                 \
        if (seg < 2048) {                                                        \
            int row = seg >> 3, sgi = seg & 7;                                   \
            uint32_t off = (uint32_t)(row * 128 + sgi * 16);                     \
            cp_async16(base + SWZ(off),                                          \
                       &g_apack[(size_t)(rb + row) * KPACK + kc0 + sgi * 8]);    \
        } else {                                                                 \
            int bseg = seg - 2048;                                               \
            int row = bseg >> 3, sgi = bseg & 7;                                 \
            uint32_t off = (uint32_t)(row * 128 + sgi * 16);                     \
            cp_async16(base + A_BYTES + SWZ(off),                                \
                       &g_bpack[(size_t)(cb + row) * KPACK + kc0 + sgi * 8]);    \
        }                                                                        \
    }                                                                            \
} while (0)

    LOAD_CHUNK(0, 0);
    CP_COMMIT();

#pragma unroll 1
    for (int c = 0; c < 4; c++) {
        int buf = c & 1;
        if (c < 3) {
            LOAD_CHUNK(c + 1, buf ^ 1);
            CP_COMMIT();
            CP_WAIT(1);
        } else {
            CP_WAIT(0);
        }
        __syncthreads();

        uint32_t abase = sbase + buf * BUF_BYTES;
        uint32_t bbase = abase + A_BYTES;
#pragma unroll
        for (int ks = 0; ks < 4; ks++) {
            uint32_t a[4][4], b[4][4];
#pragma unroll
            for (int mt = 0; mt < 4; mt++) {
                int row = wm * 64 + mt * 16 + (lane & 15);
                uint32_t off = (uint32_t)(row * 128 + ks * 32 + ((lane >> 4) & 1) * 16);
                ldsm_x4(a[mt][0], a[mt][1], a[mt][2], a[mt][3], abase + SWZ(off));
            }
#pragma unroll
            for (int nt = 0; nt < 4; nt++) {
                int row = wn * 64 + nt * 16 + (lane & 15);
                uint32_t off = (uint32_t)(row * 128 + ks * 32 + ((lane >> 4) & 1) * 16);
                ldsm_x4(b[nt][0], b[nt][1], b[nt][2], b[nt][3], bbase + SWZ(off));
            }
#pragma unroll
            for (int mt = 0; mt < 4; mt++)
#pragma unroll
                for (int nt = 0; nt < 4; nt++) {
                    mma_f16(acc[mt][nt * 2][0], acc[mt][nt * 2][1],
                            acc[mt][nt * 2][2], acc[mt][nt * 2][3],
                            a[mt][0], a[mt][1], a[mt][2], a[mt][3],
                            b[nt][0], b[nt][2]);
                    mma_f16(acc[mt][nt * 2 + 1][0], acc[mt][nt * 2 + 1][1],
                            acc[mt][nt * 2 + 1][2], acc[mt][nt * 2 + 1][3],
                            a[mt][0], a[mt][1], a[mt][2], a[mt][3],
                            b[nt][1], b[nt][3]);
                }
        }
        __syncthreads();
    }

#pragma unroll
    for (int mt = 0; mt < 4; mt++) {
#pragma unroll
        for (int nt = 0; nt < 8; nt++) {
            int row = rb + wm * 64 + mt * 16 + (lane >> 2);
            int col = cb + wn * 64 + nt * 8 + (lane & 3) * 2;
            *(float2*)&adj[(size_t)row * 8192 + col] =
                make_float2(acc[mt][nt][0], acc[mt][nt][1]);
            *(float2*)&adj[(size_t)(row + 8) * 8192 + col] =
                make_float2(acc[mt][nt][2], acc[mt][nt][3]);
        }
    }
}

// ---------------- launch: forked-capture two-arm schedule ----------------
extern "C" void kernel_launch(void* const* d_in, const int* in_sizes, int n_in,
                              void* d_out, int out_size) {
    (void)in_sizes; (void)n_in;
    const float* x  = (const float*)d_in[0];
    const void*  ei = d_in[1];
    const float *Ws = (const float*)d_in[2],  *bs  = (const float*)d_in[3];
    const float *Wt = (const float*)d_in[4],  *bt  = (const float*)d_in[5];
    const float *W1 = (const float*)d_in[6],  *b1  = (const float*)d_in[7];
    const float *W2 = (const float*)d_in[8],  *b2  = (const float*)d_in[9];
    const float *Wmu= (const float*)d_in[10], *bmu = (const float*)d_in[11];
    const float *W5 = (const float*)d_in[12], *b5  = (const float*)d_in[13];
    const float *W6 = (const float*)d_in[14], *b6  = (const float*)d_in[15];

    float* adj  = (float*)d_out;
    float* hout = (float*)d_out + ((size_t)out_size - (size_t)N_NODES * C_CH);

    cudaFuncSetAttribute(k_decoder, cudaFuncAttributeMaxDynamicSharedMemorySize,
                         DEC_SMEM);

    cudaStream_t sB;
    cudaStreamCreateWithFlags(&sB, cudaStreamNonBlocking);
    cudaEvent_t evStart, evPre, evB;
    cudaEventCreateWithFlags(&evStart, cudaEventDisableTiming);
    cudaEventCreateWithFlags(&evPre,   cudaEventDisableTiming);
    cudaEventCreateWithFlags(&evB,     cudaEventDisableTiming);

    // ---- fork anchor ----
    cudaEventRecord(evStart, 0);
    cudaStreamWaitEvent(sB, evStart, 0);

    // ---- arm B (side stream): first NodeModel gemm needs only x ----
    k_gemm_small<<<128, 256, 0, sB>>>(x, 0, W1, 0);

    // ---- main stream: graph preprocessing ----
    k_detect<<<1, 256>>>((const int*)ei);
    k_zero_cnt<<<N_NODES / 256, 256>>>();
    k_deg<<<N_EDGES / 256, 256>>>(ei);
    k_dis<<<N_NODES / 256, 256>>>();
    k_scan<<<1, 1024>>>();
    k_fill<<<N_EDGES / 256, 256>>>(ei);
    cudaEventRecord(evPre, 0);

    // ---- arm B continues after preprocessing: NodeModel chain ----
    cudaStreamWaitEvent(sB, evPre, 0);
    k_agg<<<1024, 256, 0, sB>>>(b1,  nullptr, 3, 1, 0);
    k_gemm_small<<<128, 256, 0, sB>>>(nullptr, 3, W2, 0);
    k_agg<<<1024, 256, 0, sB>>>(b2,  nullptr, 4, 1, 0);
    k_gemm_small<<<128, 256, 0, sB>>>(nullptr, 4, Wmu, 0);
    k_agg<<<1024, 256, 0, sB>>>(bmu, nullptr, 3, 0, 0);
    k_gemm_small<<<128, 256, 0, sB>>>(nullptr, 3, W5, 0);
    k_agg<<<1024, 256, 0, sB>>>(b5,  nullptr, 4, 1, 0);
    k_gemm_small<<<128, 256, 0, sB>>>(nullptr, 4, W6, 0);
    k_agg<<<1024, 256, 0, sB>>>(b6,  hout,    0, 1, 0);
    cudaEventRecord(evB, sB);

    // ---- arm A (main stream): encoder layers -> split -> decoder ----
    k_gemm_small<<<128, 256>>>(x, 0, Ws, 5);
    k_agg<<<1024, 256>>>(bs, nullptr, 1, 0, 5);
    k_gemm_small<<<128, 256>>>(x, 0, Wt, 5);
    k_agg<<<1024, 256>>>(bt, nullptr, 2, 0, 5);
    k_split<<<(N_NODES * C_CH) / 256, 256>>>();
    k_decoder<<<dim3(64, 32), 256, DEC_SMEM>>>(adj);

    // ---- join ----
    cudaStreamWaitEvent(0, evB, 0);
}